// round 1
// baseline (speedup 1.0000x reference)
#include <cuda_runtime.h>
#include <cmath>

#define NS 4096
#define NT 4096

// Per-block partial sums (4 col-chunks x 4096 rows). Written every launch by
// every block -> no init kernel, no atomics, deterministic.
__device__ float g_partials[4 * NS];

__global__ __launch_bounds__(256) void bs_main(const float* __restrict__ V,
                                               float C1f, float dLf) {
    const int i    = blockIdx.y;
    const int tid  = threadIdx.x;
    const int lane = tid & 31;
    const int jbase = blockIdx.x * 1024 + tid * 4;

    // ---- exact-representable stencil constants ----
    const float IDU2 = 16769025.0f;   // 4095^2 = 1/DU^2 (exact, < 2^24)
    const float I2DU = 2047.5f;       // 4095/2  = 1/(2*DU)
    const float IDT2 = 102375.0f;     // 4095/0.04 = 1/(2*DT_NORM)
    const float ALPHAf = 2.5f;        // 2r/sigma^2
    const float W_PDE = 1.0f / (4094.0f * 4094.0f);
    const float W_BC  = 10.0f / (float)NT;
    const float W_TC  = 10.0f / (float)NS;

    // ---- per-row stretch-metric coefficients (cheap, once per thread) ----
    const float u   = (float)i * (1.0f / 4095.0f);
    const float L   = fmaf(dLf, u, C1f);
    const float L2  = L * L;
    const float S   = fmaf(30.0f, fmaf(L2 * L, (1.0f / 6.0f), L), 100.0f);
    const float dS  = 30.0f * dLf * fmaf(0.5f, L2, 1.0f);
    const float d2S = 30.0f * dLf * dLf * L;
    const float sn   = S   * (1.0f / 300.0f);
    const float sun  = dS  * (1.0f / 300.0f);
    const float suun = d2S * (1.0f / 300.0f);
    const float inv_sun  = 1.0f / sun;
    const float inv_sun2 = inv_sun * inv_sun;
    const float pA = IDU2 * inv_sun2;              // multiplies (V[i+1]-2V+V[i-1])
    const float pB = I2DU * suun * inv_sun2 * inv_sun; // multiplies (V[i+1]-V[i-1])
    const float rC = ALPHAf * sn * I2DU * inv_sun; // alpha*S*V_S coefficient
    const float sn2 = sn * sn;

    const float4* rowC = reinterpret_cast<const float4*>(V + (size_t)i * NT);
    const int jv = jbase >> 2;
    const float4 c = rowC[jv];

    float accp = 0.0f;   // raw PDE residual^2 sum
    float acc  = 0.0f;   // pre-weighted BC + TC sums

    if (i > 0 && i < NS - 1) {
        const float4* rowU = reinterpret_cast<const float4*>(V + (size_t)(i - 1) * NT);
        const float4* rowD = reinterpret_cast<const float4*>(V + (size_t)(i + 1) * NT);
        const float4 up = rowU[jv];
        const float4 dn = rowD[jv];

        // j-1 / j+1 neighbors via warp shuffle; warp-edge lanes do scalar loads.
        float lf = __shfl_up_sync(0xffffffffu, c.w, 1);
        float rt = __shfl_down_sync(0xffffffffu, c.x, 1);
        if (lane == 0)  lf = (jbase > 0)       ? V[(size_t)i * NT + jbase - 1] : c.x;
        if (lane == 31) rt = (jbase + 4 < NT)  ? V[(size_t)i * NT + jbase + 4] : c.w;

        const float vc[4] = {c.x, c.y, c.z, c.w};
        const float vu[4] = {up.x, up.y, up.z, up.w};
        const float vd[4] = {dn.x, dn.y, dn.z, dn.w};
        const float vl[4] = {lf, c.x, c.y, c.z};
        const float vr[4] = {c.y, c.z, c.w, rt};

        #pragma unroll
        for (int k = 0; k < 4; k++) {
            const float du  = vd[k] - vu[k];
            const float suu = fmaf(-2.0f, vc[k], vd[k]) + vu[k];
            float vss = fmaf(-du, pB, suu * pA);
            vss = fminf(fmaxf(vss, -100.0f), 100.0f);
            float res = fmaf(ALPHAf, vc[k], (vr[k] - vl[k]) * IDT2);
            res = fmaf(-sn2, vss, res);
            res = fmaf(-rC, du, res);
            const int j = jbase + k;
            if (j >= 1 && j <= NT - 2)
                accp = fmaf(res, res, accp);
        }
    }

    if (i == NS - 1) {
        // far-field BC: (V[-1, j] - (1 - (K/S_MAX) e^{-r(1-t_j)}))^2
        const float vc[4] = {c.x, c.y, c.z, c.w};
        #pragma unroll
        for (int k = 0; k < 4; k++) {
            const float tj = (float)(jbase + k) * (1.0f / 4095.0f);
            const float bc = fmaf(-(100.0f / 300.0f), expf(-0.05f * (1.0f - tj)), 1.0f);
            const float d = vc[k] - bc;
            acc = fmaf(W_BC * d, d, acc);
        }
    }

    if (jbase + 3 == NT - 1) {
        // terminal Huber at t = T for this row (element k = 3)
        const float x  = 50.0f * (u - (float)(100.0 / 300.0));
        const float sp = fmaxf(x, 0.0f) + log1pf(expf(-fabsf(x)));
        const float d  = c.w - sp * 0.02f;
        const float a  = fabsf(d);
        const float h  = (a < 0.01f) ? 0.5f * d * d : 0.01f * (a - 0.005f);
        acc = fmaf(W_TC, h, acc);
    }

    // ---- block reduction ----
    float partial = fmaf(accp, W_PDE, acc);
    #pragma unroll
    for (int off = 16; off > 0; off >>= 1)
        partial += __shfl_down_sync(0xffffffffu, partial, off);

    __shared__ float sred[8];
    if (lane == 0) sred[tid >> 5] = partial;
    __syncthreads();
    if (tid < 8) {
        float v = sred[tid];
        #pragma unroll
        for (int off = 4; off > 0; off >>= 1)
            v += __shfl_down_sync(0x000000ffu, v, off);
        if (tid == 0)
            g_partials[blockIdx.y * 4 + blockIdx.x] = v;
    }
}

__global__ __launch_bounds__(1024) void bs_reduce(float* __restrict__ out) {
    const int tid  = threadIdx.x;
    const int lane = tid & 31;
    double s = 0.0;
    for (int k = tid; k < 4 * NS; k += 1024)
        s += (double)g_partials[k];
    #pragma unroll
    for (int off = 16; off > 0; off >>= 1)
        s += __shfl_down_sync(0xffffffffu, s, off);
    __shared__ double sm[32];
    if (lane == 0) sm[tid >> 5] = s;
    __syncthreads();
    if (tid < 32) {
        double v = sm[tid];
        #pragma unroll
        for (int off = 16; off > 0; off >>= 1)
            v += __shfl_down_sync(0xffffffffu, v, off);
        if (tid == 0) out[0] = (float)v;
    }
}

static double solve_depressed_cubic(double Q) {
    // Faithful port of the reference formula (including its quirks).
    const double p = 6.0;
    const double q = 6.0 * Q;
    const double sp = sqrt(p);
    double arg = fabs(q) / (2.0 * p * sp / (3.0 * sqrt(3.0)));
    if (arg < 1.0) arg = 1.0;
    const double c = 2.0 * sp * cosh(acosh(arg) / 3.0);
    return (q >= 0.0) ? -c : c;
}

extern "C" void kernel_launch(void* const* d_in, const int* in_sizes, int n_in,
                              void* d_out, int out_size) {
    const float* V = (const float*)d_in[0];
    float* out = (float*)d_out;

    const double C1 = solve_depressed_cubic((100.0 - 0.0) / 30.0);
    const double C2 = solve_depressed_cubic((100.0 - 300.0) / 30.0);

    dim3 grid(4, NS);
    bs_main<<<grid, 256>>>(V, (float)C1, (float)(C2 - C1));
    bs_reduce<<<1, 1024>>>(out);
}

// round 3
// speedup vs baseline: 1.0444x; 1.0444x over previous
#include <cuda_runtime.h>
#include <cmath>

#define NS 4096
#define NT 4096
#define RPB 16                     // rows per block
#define NBLK ((NS / RPB) * 4)     // 1024 blocks total

__device__ float4 g_coef[NS];          // pA, pB, rC, sn2 per row
__device__ float g_partials[NBLK];
__device__ unsigned int g_count = 0;

// ---- per-row stretch-metric coefficients ----
__global__ __launch_bounds__(256) void bs_coef(float C1f, float dLf) {
    const int i = blockIdx.x * 256 + threadIdx.x;
    const float IDU2 = 16769025.0f;   // 4095^2
    const float I2DU = 2047.5f;       // 4095/2
    const float ALPHAf = 2.5f;

    const float u   = (float)i * (1.0f / 4095.0f);
    const float L   = fmaf(dLf, u, C1f);
    const float L2  = L * L;
    const float S   = fmaf(30.0f, fmaf(L2 * L, (1.0f / 6.0f), L), 100.0f);
    const float dS  = 30.0f * dLf * fmaf(0.5f, L2, 1.0f);
    const float d2S = 30.0f * dLf * dLf * L;
    const float sn   = S   * (1.0f / 300.0f);
    const float sun  = dS  * (1.0f / 300.0f);
    const float suun = d2S * (1.0f / 300.0f);
    const float inv_sun  = 1.0f / sun;
    const float inv_sun2 = inv_sun * inv_sun;
    g_coef[i] = make_float4(IDU2 * inv_sun2,
                            I2DU * suun * inv_sun2 * inv_sun,
                            ALPHAf * sn * I2DU * inv_sun,
                            sn * sn);
}

__global__ __launch_bounds__(256) void bs_main(const float* __restrict__ V,
                                               float* __restrict__ out) {
    const int tid  = threadIdx.x;
    const int lane = tid & 31;
    const int r0   = blockIdx.y * RPB;
    const int jbase = blockIdx.x * 1024 + tid * 4;
    const int jv = jbase >> 2;

    const float IDT2 = 102375.0f;     // 4095/0.04 = 1/(2*DT_NORM)
    const float ALPHAf = 2.5f;
    const float W_PDE = 1.0f / (4094.0f * 4094.0f);
    const float W_BC  = 10.0f / (float)NT;
    const float W_TC  = 10.0f / (float)NS;

    const float4* Vv = reinterpret_cast<const float4*>(V);
    const int rowStride = NT / 4;

    float4 vu = Vv[(size_t)max(r0 - 1, 0) * rowStride + jv];
    float4 vc = Vv[(size_t)r0 * rowStride + jv];

    float accp = 0.0f;   // raw PDE residual^2 sum
    float acc  = 0.0f;   // pre-weighted BC + TC sums

    #pragma unroll
    for (int s = 0; s < RPB; s++) {
        const int i = r0 + s;
        const float4 vd = Vv[(size_t)min(i + 1, NS - 1) * rowStride + jv];

        if (i > 0 && i < NS - 1) {
            const float4 cf = g_coef[i];   // warp-uniform broadcast

            float lf = __shfl_up_sync(0xffffffffu, vc.w, 1);
            float rt = __shfl_down_sync(0xffffffffu, vc.x, 1);
            if (lane == 0)  lf = (jbase > 0)      ? V[(size_t)i * NT + jbase - 1] : vc.x;
            if (lane == 31) rt = (jbase + 4 < NT) ? V[(size_t)i * NT + jbase + 4] : vc.w;

            const float cc[4] = {vc.x, vc.y, vc.z, vc.w};
            const float uu[4] = {vu.x, vu.y, vu.z, vu.w};
            const float dd[4] = {vd.x, vd.y, vd.z, vd.w};
            const float ll[4] = {lf, vc.x, vc.y, vc.z};
            const float rr[4] = {vc.y, vc.z, vc.w, rt};

            #pragma unroll
            for (int k = 0; k < 4; k++) {
                const float du  = dd[k] - uu[k];
                const float suu = fmaf(-2.0f, cc[k], dd[k]) + uu[k];
                float vss = fmaf(-du, cf.y, suu * cf.x);
                vss = fminf(fmaxf(vss, -100.0f), 100.0f);
                float res = fmaf(ALPHAf, cc[k], (rr[k] - ll[k]) * IDT2);
                res = fmaf(-cf.w, vss, res);
                res = fmaf(-cf.z, du, res);
                const int j = jbase + k;
                if (j >= 1 && j <= NT - 2)
                    accp = fmaf(res, res, accp);
            }
        }

        if (i == NS - 1) {
            const float cc[4] = {vc.x, vc.y, vc.z, vc.w};
            #pragma unroll
            for (int k = 0; k < 4; k++) {
                const float tj = (float)(jbase + k) * (1.0f / 4095.0f);
                const float bc = fmaf(-(100.0f / 300.0f), expf(-0.05f * (1.0f - tj)), 1.0f);
                const float d = cc[k] - bc;
                acc = fmaf(W_BC * d, d, acc);
            }
        }

        if (jbase + 3 == NT - 1) {
            const float u  = (float)i * (1.0f / 4095.0f);
            const float x  = 50.0f * (u - (float)(100.0 / 300.0));
            const float sp = fmaxf(x, 0.0f) + log1pf(expf(-fabsf(x)));
            const float d  = vc.w - sp * 0.02f;
            const float a  = fabsf(d);
            const float h  = (a < 0.01f) ? 0.5f * d * d : 0.01f * (a - 0.005f);
            acc = fmaf(W_TC, h, acc);
        }

        vu = vc;
        vc = vd;
    }

    // ---- block reduction (float, fixed order) ----
    float partial = fmaf(accp, W_PDE, acc);
    #pragma unroll
    for (int off = 16; off > 0; off >>= 1)
        partial += __shfl_down_sync(0xffffffffu, partial, off);

    __shared__ float sred[8];
    __shared__ bool isLast;
    if (lane == 0) sred[tid >> 5] = partial;
    __syncthreads();
    if (tid < 8) {
        float v = sred[tid];
        #pragma unroll
        for (int off = 4; off > 0; off >>= 1)
            v += __shfl_down_sync(0x000000ffu, v, off);
        if (tid == 0) {
            g_partials[blockIdx.y * 4 + blockIdx.x] = v;
            __threadfence();
            const unsigned int n = atomicAdd(&g_count, 1u);
            isLast = (n == (unsigned int)(NBLK - 1));
        }
    }
    __syncthreads();

    // ---- last block performs the deterministic final sum in double ----
    if (isLast) {
        __threadfence();
        double s = 0.0;
        #pragma unroll
        for (int k = 0; k < NBLK / 256; k++)
            s += (double)g_partials[k * 256 + tid];
        #pragma unroll
        for (int off = 16; off > 0; off >>= 1)
            s += __shfl_down_sync(0xffffffffu, s, off);
        __shared__ double sm[8];
        if (lane == 0) sm[tid >> 5] = s;
        __syncthreads();
        if (tid < 8) {
            double v = sm[tid];
            #pragma unroll
            for (int off = 4; off > 0; off >>= 1)
                v += __shfl_down_sync(0x000000ffu, v, off);
            if (tid == 0) {
                out[0] = (float)v;
                g_count = 0;   // reset for next (graph-replayed) launch
            }
        }
    }
}

static double solve_depressed_cubic(double Q) {
    const double p = 6.0;
    const double q = 6.0 * Q;
    const double sp = sqrt(p);
    double arg = fabs(q) / (2.0 * p * sp / (3.0 * sqrt(3.0)));
    if (arg < 1.0) arg = 1.0;
    const double c = 2.0 * sp * cosh(acosh(arg) / 3.0);
    return (q >= 0.0) ? -c : c;
}

extern "C" void kernel_launch(void* const* d_in, const int* in_sizes, int n_in,
                              void* d_out, int out_size) {
    const float* V = (const float*)d_in[0];
    float* out = (float*)d_out;

    const double C1 = solve_depressed_cubic((100.0 - 0.0) / 30.0);
    const double C2 = solve_depressed_cubic((100.0 - 300.0) / 30.0);

    bs_coef<<<NS / 256, 256>>>((float)C1, (float)(C2 - C1));
    dim3 grid(4, NS / RPB);
    bs_main<<<grid, 256>>>(V, out);
}

// round 4
// speedup vs baseline: 1.4200x; 1.3596x over previous
#include <cuda_runtime.h>
#include <cmath>

#define NS 4096
#define NT 4096
#define RPB 32                     // rows per block
#define NBLK ((NS / RPB) * 4)      // 512 blocks total

__device__ float4 g_coef[NS];          // pA, pB, rC, sn2 per row
__device__ float g_partials[NBLK];
__device__ unsigned int g_count = 0;

// ---- per-row stretch-metric coefficients ----
__global__ __launch_bounds__(256) void bs_coef(float C1f, float dLf) {
    const int i = blockIdx.x * 256 + threadIdx.x;
    const float IDU2 = 16769025.0f;   // 4095^2
    const float I2DU = 2047.5f;       // 4095/2
    const float ALPHAf = 2.5f;

    const float u   = (float)i * (1.0f / 4095.0f);
    const float L   = fmaf(dLf, u, C1f);
    const float L2  = L * L;
    const float S   = fmaf(30.0f, fmaf(L2 * L, (1.0f / 6.0f), L), 100.0f);
    const float dS  = 30.0f * dLf * fmaf(0.5f, L2, 1.0f);
    const float d2S = 30.0f * dLf * dLf * L;
    const float sn   = S   * (1.0f / 300.0f);
    const float sun  = dS  * (1.0f / 300.0f);
    const float suun = d2S * (1.0f / 300.0f);
    const float inv_sun  = 1.0f / sun;
    const float inv_sun2 = inv_sun * inv_sun;
    g_coef[i] = make_float4(IDU2 * inv_sun2,
                            I2DU * suun * inv_sun2 * inv_sun,
                            ALPHAf * sn * I2DU * inv_sun,
                            sn * sn);
}

__global__ __launch_bounds__(256) void bs_main(const float* __restrict__ V,
                                               float* __restrict__ out) {
    const int tid  = threadIdx.x;
    const int lane = tid & 31;
    const int r0   = blockIdx.y * RPB;
    const int jbase = blockIdx.x * 1024 + tid * 4;
    const int jv = jbase >> 2;

    const float IDT2 = 102375.0f;     // 4095/0.04 = 1/(2*DT_NORM)
    const float ALPHAf = 2.5f;
    const float W_PDE = 1.0f / (4094.0f * 4094.0f);
    const float W_BC  = 10.0f / (float)NT;
    const float W_TC  = 10.0f / (float)NS;

    const float4* Vv = reinterpret_cast<const float4*>(V);
    const int rowStride = NT / 4;

    // interior-j mask, loop-invariant per thread
    const bool mL = (jbase >= 1);           // k=0 valid iff jbase>=1
    const bool mR = (jbase + 3 <= NT - 2);  // k=3 valid iff jbase+3<=NT-2

    float4 vu = Vv[(size_t)max(r0 - 1, 0) * rowStride + jv];
    float4 vc = Vv[(size_t)r0 * rowStride + jv];
    float4 vp = Vv[(size_t)min(r0 + 1, NS - 1) * rowStride + jv];  // prefetched row

    float accp0 = 0.0f, accp1 = 0.0f;   // raw PDE residual^2 sums (2 chains)
    float acc   = 0.0f;                 // pre-weighted BC + TC sums

    #pragma unroll 8
    for (int s = 0; s < RPB; s++) {
        const int i = r0 + s;
        const float4 vd = vp;
        // prefetch the row needed two iterations from now
        vp = Vv[(size_t)min(i + 2, NS - 1) * rowStride + jv];

        if (i > 0 && i < NS - 1) {
            const float4 cf = g_coef[i];   // warp-uniform broadcast

            float lf = __shfl_up_sync(0xffffffffu, vc.w, 1);
            float rt = __shfl_down_sync(0xffffffffu, vc.x, 1);
            if (lane == 0)  lf = (jbase > 0)      ? __ldg(V + (size_t)i * NT + jbase - 1) : vc.x;
            if (lane == 31) rt = (jbase + 4 < NT) ? __ldg(V + (size_t)i * NT + jbase + 4) : vc.w;

            const float cc[4] = {vc.x, vc.y, vc.z, vc.w};
            const float uu[4] = {vu.x, vu.y, vu.z, vu.w};
            const float dd[4] = {vd.x, vd.y, vd.z, vd.w};
            const float ll[4] = {lf, vc.x, vc.y, vc.z};
            const float rr[4] = {vc.y, vc.z, vc.w, rt};

            #pragma unroll
            for (int k = 0; k < 4; k++) {
                const float du  = dd[k] - uu[k];
                const float suu = fmaf(-2.0f, cc[k], dd[k]) + uu[k];
                float vss = fmaf(-du, cf.y, suu * cf.x);
                vss = fminf(fmaxf(vss, -100.0f), 100.0f);
                float res = fmaf(ALPHAf, cc[k], (rr[k] - ll[k]) * IDT2);
                res = fmaf(-cf.w, vss, res);
                res = fmaf(-cf.z, du, res);
                const bool ok = (k == 0) ? mL : ((k == 3) ? mR : true);
                if (ok) {
                    if (k & 1) accp1 = fmaf(res, res, accp1);
                    else       accp0 = fmaf(res, res, accp0);
                }
            }
        }

        if (i == NS - 1) {
            const float cc[4] = {vc.x, vc.y, vc.z, vc.w};
            #pragma unroll
            for (int k = 0; k < 4; k++) {
                const float tj = (float)(jbase + k) * (1.0f / 4095.0f);
                const float bc = fmaf(-(100.0f / 300.0f), expf(-0.05f * (1.0f - tj)), 1.0f);
                const float d = cc[k] - bc;
                acc = fmaf(W_BC * d, d, acc);
            }
        }

        if (jbase + 3 == NT - 1) {
            const float u  = (float)i * (1.0f / 4095.0f);
            const float x  = 50.0f * (u - (float)(100.0 / 300.0));
            const float sp = fmaxf(x, 0.0f) + log1pf(expf(-fabsf(x)));
            const float d  = vc.w - sp * 0.02f;
            const float a  = fabsf(d);
            const float h  = (a < 0.01f) ? 0.5f * d * d : 0.01f * (a - 0.005f);
            acc = fmaf(W_TC, h, acc);
        }

        vu = vc;
        vc = vd;
    }

    // ---- block reduction (float, fixed order) ----
    float partial = fmaf(accp0 + accp1, W_PDE, acc);
    #pragma unroll
    for (int off = 16; off > 0; off >>= 1)
        partial += __shfl_down_sync(0xffffffffu, partial, off);

    __shared__ float sred[8];
    __shared__ bool isLast;
    if (lane == 0) sred[tid >> 5] = partial;
    __syncthreads();
    if (tid < 8) {
        float v = sred[tid];
        #pragma unroll
        for (int off = 4; off > 0; off >>= 1)
            v += __shfl_down_sync(0x000000ffu, v, off);
        if (tid == 0) {
            g_partials[blockIdx.y * 4 + blockIdx.x] = v;
            __threadfence();
            const unsigned int n = atomicAdd(&g_count, 1u);
            isLast = (n == (unsigned int)(NBLK - 1));
        }
    }
    __syncthreads();

    // ---- last block performs the deterministic final sum in double ----
    if (isLast) {
        __threadfence();
        double s = 0.0;
        #pragma unroll
        for (int k = 0; k < NBLK / 256; k++)
            s += (double)g_partials[k * 256 + tid];
        #pragma unroll
        for (int off = 16; off > 0; off >>= 1)
            s += __shfl_down_sync(0xffffffffu, s, off);
        __shared__ double sm[8];
        if (lane == 0) sm[tid >> 5] = s;
        __syncthreads();
        if (tid < 8) {
            double v = sm[tid];
            #pragma unroll
            for (int off = 4; off > 0; off >>= 1)
                v += __shfl_down_sync(0x000000ffu, v, off);
            if (tid == 0) {
                out[0] = (float)v;
                g_count = 0;   // reset for next (graph-replayed) launch
            }
        }
    }
}

static double solve_depressed_cubic(double Q) {
    const double p = 6.0;
    const double q = 6.0 * Q;
    const double sp = sqrt(p);
    double arg = fabs(q) / (2.0 * p * sp / (3.0 * sqrt(3.0)));
    if (arg < 1.0) arg = 1.0;
    const double c = 2.0 * sp * cosh(acosh(arg) / 3.0);
    return (q >= 0.0) ? -c : c;
}

extern "C" void kernel_launch(void* const* d_in, const int* in_sizes, int n_in,
                              void* d_out, int out_size) {
    const float* V = (const float*)d_in[0];
    float* out = (float*)d_out;

    const double C1 = solve_depressed_cubic((100.0 - 0.0) / 30.0);
    const double C2 = solve_depressed_cubic((100.0 - 300.0) / 30.0);

    bs_coef<<<NS / 256, 256>>>((float)C1, (float)(C2 - C1));
    dim3 grid(4, NS / RPB);
    bs_main<<<grid, 256>>>(V, out);
}

// round 5
// speedup vs baseline: 1.4405x; 1.0145x over previous
#include <cuda_runtime.h>
#include <cmath>

#define NS 4096
#define NT 4096
#define RPB 32                     // rows per block
#define NBLK ((NS / RPB) * 4)      // 512 blocks total

__device__ float4 g_coef[NS];          // pA, pB, rC, sn2 per row
__device__ float g_partials[NBLK];
__device__ unsigned int g_count = 0;

// ---- per-row stretch-metric coefficients ----
__global__ __launch_bounds__(256) void bs_coef(float C1f, float dLf) {
    const int i = blockIdx.x * 256 + threadIdx.x;
    const float IDU2 = 16769025.0f;   // 4095^2
    const float I2DU = 2047.5f;       // 4095/2
    const float ALPHAf = 2.5f;

    const float u   = (float)i * (1.0f / 4095.0f);
    const float L   = fmaf(dLf, u, C1f);
    const float L2  = L * L;
    const float S   = fmaf(30.0f, fmaf(L2 * L, (1.0f / 6.0f), L), 100.0f);
    const float dS  = 30.0f * dLf * fmaf(0.5f, L2, 1.0f);
    const float d2S = 30.0f * dLf * dLf * L;
    const float sn   = S   * (1.0f / 300.0f);
    const float sun  = dS  * (1.0f / 300.0f);
    const float suun = d2S * (1.0f / 300.0f);
    const float inv_sun  = 1.0f / sun;
    const float inv_sun2 = inv_sun * inv_sun;
    g_coef[i] = make_float4(IDU2 * inv_sun2,
                            I2DU * suun * inv_sun2 * inv_sun,
                            ALPHAf * sn * I2DU * inv_sun,
                            sn * sn);
}

__global__ __launch_bounds__(256) void bs_main(const float* __restrict__ V,
                                               float* __restrict__ out) {
    const int tid  = threadIdx.x;
    const int lane = tid & 31;
    const int r0   = blockIdx.y * RPB;
    const int jbase = blockIdx.x * 1024 + tid * 4;
    const int jv = jbase >> 2;

    const float IDT2 = 102375.0f;     // 4095/0.04 = 1/(2*DT_NORM)
    const float ALPHAf = 2.5f;
    const float W_PDE = 1.0f / (4094.0f * 4094.0f);
    const float W_BC  = 10.0f / (float)NT;
    const float W_TC  = 10.0f / (float)NS;

    const float4* Vv = reinterpret_cast<const float4*>(V);
    const int rowStride = NT / 4;

    // clamped neighbor columns (masked at j edges, so values don't matter)
    const int jl = max(jbase - 1, 0);
    const int jr = min(jbase + 4, NT - 1);
    const bool mL = (jbase >= 1);           // k=0 valid iff jbase>=1
    const bool mR = (jbase + 3 <= NT - 2);  // k=3 valid iff jbase+3<=NT-2

    // ---- prologue: depth-2 row pipeline + neighbor scalars for row r0 ----
    float4 vu = Vv[(size_t)max(r0 - 1, 0) * rowStride + jv];
    float4 vc = Vv[(size_t)r0 * rowStride + jv];
    float4 p0 = Vv[(size_t)min(r0 + 1, NS - 1) * rowStride + jv];
    float4 p1 = Vv[(size_t)min(r0 + 2, NS - 1) * rowStride + jv];
    float  lf = V[(size_t)r0 * NT + jl];
    float  rt = V[(size_t)r0 * NT + jr];

    float accp0 = 0.0f, accp1 = 0.0f;   // raw PDE residual^2 sums (2 chains)
    float acc   = 0.0f;                 // pre-weighted BC + TC sums

    #pragma unroll 8
    for (int s = 0; s < RPB; s++) {
        const int i = r0 + s;
        const float4 vd = p0;
        p0 = p1;
        // prefetch: row i+3 (float4) and row i+1's neighbor scalars
        p1 = Vv[(size_t)min(i + 3, NS - 1) * rowStride + jv];
        const size_t nrow = (size_t)min(i + 1, NS - 1) * NT;
        const float lfN = V[nrow + jl];
        const float rtN = V[nrow + jr];

        if (i > 0 && i < NS - 1) {
            const float4 cf = g_coef[i];   // warp-uniform broadcast

            const float cc[4] = {vc.x, vc.y, vc.z, vc.w};
            const float uu[4] = {vu.x, vu.y, vu.z, vu.w};
            const float dd[4] = {vd.x, vd.y, vd.z, vd.w};
            const float ll[4] = {lf, vc.x, vc.y, vc.z};
            const float rr[4] = {vc.y, vc.z, vc.w, rt};

            #pragma unroll
            for (int k = 0; k < 4; k++) {
                const float du  = dd[k] - uu[k];
                const float suu = fmaf(-2.0f, cc[k], dd[k]) + uu[k];
                float vss = fmaf(-du, cf.y, suu * cf.x);
                vss = fminf(fmaxf(vss, -100.0f), 100.0f);
                float res = fmaf(ALPHAf, cc[k], (rr[k] - ll[k]) * IDT2);
                res = fmaf(-cf.w, vss, res);
                res = fmaf(-cf.z, du, res);
                const bool ok = (k == 0) ? mL : ((k == 3) ? mR : true);
                if (ok) {
                    if (k & 1) accp1 = fmaf(res, res, accp1);
                    else       accp0 = fmaf(res, res, accp0);
                }
            }
        }

        if (i == NS - 1) {
            const float cc[4] = {vc.x, vc.y, vc.z, vc.w};
            #pragma unroll
            for (int k = 0; k < 4; k++) {
                const float tj = (float)(jbase + k) * (1.0f / 4095.0f);
                const float bc = fmaf(-(100.0f / 300.0f), expf(-0.05f * (1.0f - tj)), 1.0f);
                const float d = cc[k] - bc;
                acc = fmaf(W_BC * d, d, acc);
            }
        }

        if (jbase + 3 == NT - 1) {
            const float u  = (float)i * (1.0f / 4095.0f);
            const float x  = 50.0f * (u - (float)(100.0 / 300.0));
            const float sp = fmaxf(x, 0.0f) + log1pf(expf(-fabsf(x)));
            const float d  = vc.w - sp * 0.02f;
            const float a  = fabsf(d);
            const float h  = (a < 0.01f) ? 0.5f * d * d : 0.01f * (a - 0.005f);
            acc = fmaf(W_TC, h, acc);
        }

        vu = vc;
        vc = vd;
        lf = lfN;
        rt = rtN;
    }

    // ---- block reduction (float, fixed order) ----
    float partial = fmaf(accp0 + accp1, W_PDE, acc);
    #pragma unroll
    for (int off = 16; off > 0; off >>= 1)
        partial += __shfl_down_sync(0xffffffffu, partial, off);

    __shared__ float sred[8];
    __shared__ bool isLast;
    if (lane == 0) sred[tid >> 5] = partial;
    __syncthreads();
    if (tid < 8) {
        float v = sred[tid];
        #pragma unroll
        for (int off = 4; off > 0; off >>= 1)
            v += __shfl_down_sync(0x000000ffu, v, off);
        if (tid == 0) {
            g_partials[blockIdx.y * 4 + blockIdx.x] = v;
            __threadfence();
            const unsigned int n = atomicAdd(&g_count, 1u);
            isLast = (n == (unsigned int)(NBLK - 1));
        }
    }
    __syncthreads();

    // ---- last block performs the deterministic final sum in double ----
    if (isLast) {
        __threadfence();
        double s = 0.0;
        #pragma unroll
        for (int k = 0; k < NBLK / 256; k++)
            s += (double)g_partials[k * 256 + tid];
        #pragma unroll
        for (int off = 16; off > 0; off >>= 1)
            s += __shfl_down_sync(0xffffffffu, s, off);
        __shared__ double sm[8];
        if (lane == 0) sm[tid >> 5] = s;
        __syncthreads();
        if (tid < 8) {
            double v = sm[tid];
            #pragma unroll
            for (int off = 4; off > 0; off >>= 1)
                v += __shfl_down_sync(0x000000ffu, v, off);
            if (tid == 0) {
                out[0] = (float)v;
                g_count = 0;   // reset for next (graph-replayed) launch
            }
        }
    }
}

static double solve_depressed_cubic(double Q) {
    const double p = 6.0;
    const double q = 6.0 * Q;
    const double sp = sqrt(p);
    double arg = fabs(q) / (2.0 * p * sp / (3.0 * sqrt(3.0)));
    if (arg < 1.0) arg = 1.0;
    const double c = 2.0 * sp * cosh(acosh(arg) / 3.0);
    return (q >= 0.0) ? -c : c;
}

extern "C" void kernel_launch(void* const* d_in, const int* in_sizes, int n_in,
                              void* d_out, int out_size) {
    const float* V = (const float*)d_in[0];
    float* out = (float*)d_out;

    const double C1 = solve_depressed_cubic((100.0 - 0.0) / 30.0);
    const double C2 = solve_depressed_cubic((100.0 - 300.0) / 30.0);

    bs_coef<<<NS / 256, 256>>>((float)C1, (float)(C2 - C1));
    dim3 grid(4, NS / RPB);
    bs_main<<<grid, 256>>>(V, out);
}